// round 1
// baseline (speedup 1.0000x reference)
#include <cuda_runtime.h>
#include <float.h>

#define H_   4
#define CPH  32
#define CIN  128
#define NMAX 50048

// ---------------- device scratch (no allocs allowed) ----------------
__device__ float4   g_w4[2 * H_ * CIN / 4];   // [sel][h][k] folded weights, sel 0=src 1=dst
__device__ float    g_c[2 * H_];              // folded bias terms
__device__ float4   g_s[NMAX * 2];            // per node: [2n]=src scores (4 heads), [2n+1]=dst
__device__ int      g_flag;                   // 1 => edge_index is int32, 0 => int64
__device__ unsigned g_maxenc[H_];             // order-preserving encoded per-head max
__device__ float    g_partial[512 * H_];      // per-block partial exp sums
__device__ float4   g_scale;                  // 1/sum per head

// order-preserving float<->uint encoding for atomicMax
__device__ __forceinline__ unsigned enc_f(float f) {
    unsigned u = __float_as_uint(f);
    return (u & 0x80000000u) ? ~u : (u | 0x80000000u);
}
__device__ __forceinline__ float dec_f(unsigned u) {
    return (u & 0x80000000u) ? __uint_as_float(u & 0x7FFFFFFFu) : __uint_as_float(~u);
}

// ---------------- kernel 1: fold W,a,b into per-head vectors; reset state ----
__global__ void k_prep(const float* __restrict__ W, const float* __restrict__ b,
                       const float* __restrict__ a) {
    int t = threadIdx.x;             // 512 threads
    int h = t >> 7, k = t & 127;
    float ws = 0.f, wd = 0.f;
    #pragma unroll
    for (int c = 0; c < CPH; c++) {
        float w = W[(h * CPH + c) * CIN + k];
        ws += w * a[h * (2 * CPH) + c];
        wd += w * a[h * (2 * CPH) + CPH + c];
    }
    float* wf = (float*)g_w4;
    wf[h * CIN + k] = ws;
    wf[H_ * CIN + h * CIN + k] = wd;
    if (t < 2 * H_) {
        int sel = t >> 2, hh = t & 3;
        float cv = 0.f;
        #pragma unroll
        for (int c = 0; c < CPH; c++)
            cv += b[hh * CPH + c] * a[hh * (2 * CPH) + sel * CPH + c];
        g_c[t] = cv;
    }
    if (t == 0) {
        g_flag = 0;
        #pragma unroll
        for (int hh = 0; hh < H_; hh++) g_maxenc[hh] = 0u;
    }
}

// ---------------- kernel 2: detect int32 vs int64 edge_index ----------------
__global__ void k_detect(const void* __restrict__ idx) {
    int t = blockIdx.x * blockDim.x + threadIdx.x;  // 1024 threads
    long long v = ((const long long*)idx)[t];
    if ((unsigned long long)v > 0xFFFFFFFFull) atomicOr(&g_flag, 1);
}

// ---------------- kernel 3: per-node scores (warp per node) -----------------
__global__ void __launch_bounds__(256) k_nodes(const float* __restrict__ x, int N) {
    int warp = (blockIdx.x * blockDim.x + threadIdx.x) >> 5;
    int lane = threadIdx.x & 31;
    if (warp >= N) return;
    float4 xv = ((const float4*)(x + (size_t)warp * CIN))[lane];
    float acc[8];
    #pragma unroll
    for (int i = 0; i < 8; i++) {
        float4 w = g_w4[i * 32 + lane];
        acc[i] = xv.x * w.x + xv.y * w.y + xv.z * w.z + xv.w * w.w;
    }
    #pragma unroll
    for (int i = 0; i < 8; i++)
        #pragma unroll
        for (int o = 16; o; o >>= 1)
            acc[i] += __shfl_xor_sync(0xFFFFFFFFu, acc[i], o);
    if (lane == 0) {
        float4 s0 = make_float4(acc[0] + g_c[0], acc[1] + g_c[1],
                                acc[2] + g_c[2], acc[3] + g_c[3]);
        float4 s1 = make_float4(acc[4] + g_c[4], acc[5] + g_c[5],
                                acc[6] + g_c[6], acc[7] + g_c[7]);
        g_s[warp * 2]     = s0;
        g_s[warp * 2 + 1] = s1;
    }
}

// ---------------- kernel 4: logits + leaky relu + per-head max --------------
__global__ void __launch_bounds__(256) k_edge1(const void* __restrict__ idx,
                                               float* __restrict__ out, int E) {
    int e = blockIdx.x * 256 + threadIdx.x;
    float mx0 = -FLT_MAX, mx1 = -FLT_MAX, mx2 = -FLT_MAX, mx3 = -FLT_MAX;
    if (e < E) {
        int src, dst;
        if (g_flag) {
            const int* p = (const int*)idx;
            src = p[e]; dst = p[E + e];
        } else {
            const long long* p = (const long long*)idx;
            src = (int)p[e]; dst = (int)p[E + e];
        }
        float4 a4 = g_s[src * 2];
        float4 b4 = g_s[dst * 2 + 1];
        float4 l;
        l.x = a4.x + b4.x; l.y = a4.y + b4.y;
        l.z = a4.z + b4.z; l.w = a4.w + b4.w;
        l.x = fmaxf(l.x, 0.2f * l.x); l.y = fmaxf(l.y, 0.2f * l.y);
        l.z = fmaxf(l.z, 0.2f * l.z); l.w = fmaxf(l.w, 0.2f * l.w);
        ((float4*)out)[e] = l;
        mx0 = l.x; mx1 = l.y; mx2 = l.z; mx3 = l.w;
    }
    // block max reduce, then one atomicMax per head per block
    #pragma unroll
    for (int o = 16; o; o >>= 1) {
        mx0 = fmaxf(mx0, __shfl_xor_sync(0xFFFFFFFFu, mx0, o));
        mx1 = fmaxf(mx1, __shfl_xor_sync(0xFFFFFFFFu, mx1, o));
        mx2 = fmaxf(mx2, __shfl_xor_sync(0xFFFFFFFFu, mx2, o));
        mx3 = fmaxf(mx3, __shfl_xor_sync(0xFFFFFFFFu, mx3, o));
    }
    __shared__ float smax[8][4];
    int wid = threadIdx.x >> 5;
    if ((threadIdx.x & 31) == 0) {
        smax[wid][0] = mx0; smax[wid][1] = mx1;
        smax[wid][2] = mx2; smax[wid][3] = mx3;
    }
    __syncthreads();
    if (threadIdx.x < 4) {
        float m = smax[0][threadIdx.x];
        #pragma unroll
        for (int w = 1; w < 8; w++) m = fmaxf(m, smax[w][threadIdx.x]);
        atomicMax(&g_maxenc[threadIdx.x], enc_f(m));
    }
}

// ---------------- kernel 5: exp(l - max), per-block partial sums ------------
__global__ void __launch_bounds__(256) k_edge2(float* __restrict__ out, int E) {
    float m0 = dec_f(g_maxenc[0]), m1 = dec_f(g_maxenc[1]);
    float m2 = dec_f(g_maxenc[2]), m3 = dec_f(g_maxenc[3]);
    float s0 = 0.f, s1 = 0.f, s2 = 0.f, s3 = 0.f;
    float4* o4 = (float4*)out;
    for (int e = blockIdx.x * 256 + threadIdx.x; e < E; e += 512 * 256) {
        float4 l = o4[e];
        l.x = __expf(l.x - m0); l.y = __expf(l.y - m1);
        l.z = __expf(l.z - m2); l.w = __expf(l.w - m3);
        o4[e] = l;
        s0 += l.x; s1 += l.y; s2 += l.z; s3 += l.w;
    }
    #pragma unroll
    for (int o = 16; o; o >>= 1) {
        s0 += __shfl_xor_sync(0xFFFFFFFFu, s0, o);
        s1 += __shfl_xor_sync(0xFFFFFFFFu, s1, o);
        s2 += __shfl_xor_sync(0xFFFFFFFFu, s2, o);
        s3 += __shfl_xor_sync(0xFFFFFFFFu, s3, o);
    }
    __shared__ float ssum[8][4];
    int wid = threadIdx.x >> 5;
    if ((threadIdx.x & 31) == 0) {
        ssum[wid][0] = s0; ssum[wid][1] = s1;
        ssum[wid][2] = s2; ssum[wid][3] = s3;
    }
    __syncthreads();
    if (threadIdx.x < 4) {
        float s = ssum[0][threadIdx.x];
        #pragma unroll
        for (int w = 1; w < 8; w++) s += ssum[w][threadIdx.x];
        g_partial[blockIdx.x * 4 + threadIdx.x] = s;   // fixed order -> deterministic
    }
}

// ---------------- kernel 6: deterministic final sum + reciprocal ------------
__global__ void k_reduce() {
    int t = threadIdx.x;  // 128 threads
    float loc[4] = {0.f, 0.f, 0.f, 0.f};
    for (int j = t; j < 512; j += 128) {
        #pragma unroll
        for (int h = 0; h < 4; h++) loc[h] += g_partial[j * 4 + h];
    }
    #pragma unroll
    for (int h = 0; h < 4; h++)
        #pragma unroll
        for (int o = 16; o; o >>= 1)
            loc[h] += __shfl_xor_sync(0xFFFFFFFFu, loc[h], o);
    __shared__ float ss[4][4];
    int wid = t >> 5;
    if ((t & 31) == 0) {
        #pragma unroll
        for (int h = 0; h < 4; h++) ss[wid][h] = loc[h];
    }
    __syncthreads();
    if (t == 0) {
        float4 sc;
        sc.x = 1.f / (ss[0][0] + ss[1][0] + ss[2][0] + ss[3][0]);
        sc.y = 1.f / (ss[0][1] + ss[1][1] + ss[2][1] + ss[3][1]);
        sc.z = 1.f / (ss[0][2] + ss[1][2] + ss[2][2] + ss[3][2]);
        sc.w = 1.f / (ss[0][3] + ss[1][3] + ss[2][3] + ss[3][3]);
        g_scale = sc;
    }
}

// ---------------- kernel 7: normalize ---------------------------------------
__global__ void __launch_bounds__(256) k_edge3(float* __restrict__ out, int E) {
    int e = blockIdx.x * 256 + threadIdx.x;
    if (e >= E) return;
    float4 sc = g_scale;
    float4* o4 = (float4*)out;
    float4 v = o4[e];
    v.x *= sc.x; v.y *= sc.y; v.z *= sc.z; v.w *= sc.w;
    o4[e] = v;
}

extern "C" void kernel_launch(void* const* d_in, const int* in_sizes, int n_in,
                              void* d_out, int out_size) {
    const float* node_feats = (const float*)d_in[0];
    const void*  edge_index = d_in[1];
    const float* W = (const float*)d_in[2];
    const float* b = (const float*)d_in[3];
    const float* a = (const float*)d_in[4];
    float* out = (float*)d_out;

    int N = in_sizes[0] / CIN;       // 50000
    int E = in_sizes[1] / 2;         // 800000 (element count same for i32/i64)

    k_prep<<<1, 512>>>(W, b, a);
    k_detect<<<2, 512>>>(edge_index);
    k_nodes<<<(N + 7) / 8, 256>>>(node_feats, N);
    int eb = (E + 255) / 256;
    k_edge1<<<eb, 256>>>(edge_index, out, E);
    k_edge2<<<512, 256>>>(out, E);
    k_reduce<<<1, 128>>>();
    k_edge3<<<eb, 256>>>(out, E);
}